// round 3
// baseline (speedup 1.0000x reference)
#include <cuda_runtime.h>
#include <math.h>

#define D 192
#define S_SAMPLES 96
#define NWARP_PER_BLK 8
#define KW_CONST 1.6925687506f  // sqrt(9/pi)

static __device__ __forceinline__ void red_add_v2(float* addr, float a, float b) {
    asm volatile("red.global.add.v2.f32 [%0], {%1, %2};"
                 :: "l"(addr), "f"(a), "f"(b) : "memory");
}
static __device__ __forceinline__ void red_add_v4(float* addr, float a, float b, float c, float d) {
    asm volatile("red.global.add.v4.f32 [%0], {%1, %2, %3, %4};"
                 :: "l"(addr), "f"(a), "f"(b), "f"(c), "f"(d) : "memory");
}

// One fused kernel for all 3 LOR sets. Per warp: pick lors + axis permutation.
// Linear index into the ORIGINAL volume layout is always (i0*D + i1)*D + iu,
// where (axis0, axis1, axisU) is the permuted world-axis triple:
//   z-set: (x, y, z)   x-set: (y, z, x)   y-set: (y, x, z)
__global__ void __launch_bounds__(NWARP_PER_BLK * 32, 6)
lor_all_kernel(const float* __restrict__ xlors,
               const float* __restrict__ ylors,
               const float* __restrict__ zlors,
               int nx, int ny, int nz,
               const float* __restrict__ img,
               const float* __restrict__ center,
               const float* __restrict__ size,
               float* __restrict__ acc)
{
    int warp = (blockIdx.x * blockDim.x + threadIdx.x) >> 5;
    int lane = threadIdx.x & 31;
    int total = nx + ny + nz;
    if (warp >= total) return;

    const float* L;
    int perm;
    if (warp < nz)           { L = zlors + warp * 6;             perm = 0; }
    else if (warp < nz + nx) { L = xlors + (warp - nz) * 6;      perm = 1; }
    else                     { L = ylors + (warp - nz - nx) * 6; perm = 2; }

    float p1x = L[0], p1y = L[1], p1z = L[2];
    float p2x = L[3], p2y = L[4], p2z = L[5];

    float sx = size[0], sy = size[1], sz = size[2];
    float dx = p2x - p1x, dy = p2y - p1y, dz = p2z - p1z;
    float seg = sqrtf(dx * dx + dy * dy + dz * dz) * (1.0f / (float)S_SAMPLES);

    // world -> voxel line parametrization: w_a(t) = c_a + t * m_a (divisions once per warp)
    float ivx = (float)D / sx, ivy = (float)D / sy, ivz = (float)D / sz;
    float cxw = (p1x - (center[0] - 0.5f * sx)) * ivx - 0.5f;
    float cyw = (p1y - (center[1] - 0.5f * sy)) * ivy - 0.5f;
    float czw = (p1z - (center[2] - 0.5f * sz)) * ivz - 0.5f;
    float mxw = dx * ivx, myw = dy * ivy, mzw = dz * ivz;

    float c0, c1, cu, m0, m1, mu;
    if (perm == 0)      { c0 = cxw; c1 = cyw; cu = czw; m0 = mxw; m1 = myw; mu = mzw; }
    else if (perm == 1) { c0 = cyw; c1 = czw; cu = cxw; m0 = myw; m1 = mzw; mu = mxw; }
    else                { c0 = cyw; c1 = cxw; cu = czw; m0 = myw; m1 = mxw; mu = mzw; }

    // ---- gather pass: line integral ----
    float sum = 0.0f;
    #pragma unroll
    for (int k = 0; k < 3; k++) {
        float t = ((float)(lane + 32 * k) + 0.5f) * (1.0f / (float)S_SAMPLES);
        float w0 = fmaf(t, m0, c0);
        float w1 = fmaf(t, m1, c1);
        float wu = fmaf(t, mu, cu);
        float f0 = floorf(w0), f1 = floorf(w1), fu = floorf(wu);
        int i0 = (int)f0, i1 = (int)f1, iu = (int)fu;
        float r0 = w0 - f0, r1 = w1 - f1, ru = wu - fu;
        float wu0 = 1.0f - ru, wu1 = ru;
        int o = iu & 3;
        bool pair_ok = (iu >= 0) && (iu < D - 1) && (o != 3);

        #pragma unroll
        for (int c = 0; c < 4; c++) {
            int j0 = i0 + (c >> 1);
            int j1 = i1 + (c & 1);
            if ((unsigned)j0 >= (unsigned)D || (unsigned)j1 >= (unsigned)D) continue;
            float wrow = ((c & 2) ? r0 : 1.0f - r0) * ((c & 1) ? r1 : 1.0f - r1);
            int row = (j0 * D + j1) * D;
            if (pair_ok) {
                const float4 v = *reinterpret_cast<const float4*>(img + row + (iu & ~3));
                float e0 = (o == 0) ? v.x : ((o == 1) ? v.y : v.z);
                float e1 = (o == 0) ? v.y : ((o == 1) ? v.z : v.w);
                sum += wrow * (e0 * wu0 + e1 * wu1);
            } else {
                if ((unsigned)iu < (unsigned)D)       sum += img[row + iu]     * (wrow * wu0);
                if ((unsigned)(iu + 1) < (unsigned)D) sum += img[row + iu + 1] * (wrow * wu1);
            }
        }
    }

    #pragma unroll
    for (int off = 16; off > 0; off >>= 1)
        sum += __shfl_xor_sync(0xffffffffu, sum, off);

    float a = seg * KW_CONST;
    float contrib = sum * a * a;

    // ---- scatter pass: recompute coords (cheap FMAs, no cached arrays) ----
    #pragma unroll
    for (int k = 0; k < 3; k++) {
        float t = ((float)(lane + 32 * k) + 0.5f) * (1.0f / (float)S_SAMPLES);
        float w0 = fmaf(t, m0, c0);
        float w1 = fmaf(t, m1, c1);
        float wu = fmaf(t, mu, cu);
        float f0 = floorf(w0), f1 = floorf(w1), fu = floorf(wu);
        int i0 = (int)f0, i1 = (int)f1, iu = (int)fu;
        float r0 = w0 - f0, r1 = w1 - f1, ru = wu - fu;
        float wu0 = (1.0f - ru) * contrib, wu1 = ru * contrib;
        int o = iu & 3;
        bool in_pair = (iu >= 0) && (iu < D - 1);

        #pragma unroll
        for (int c = 0; c < 4; c++) {
            int j0 = i0 + (c >> 1);
            int j1 = i1 + (c & 1);
            if ((unsigned)j0 >= (unsigned)D || (unsigned)j1 >= (unsigned)D) continue;
            float wrow = ((c & 2) ? r0 : 1.0f - r0) * ((c & 1) ? r1 : 1.0f - r1);
            int row = (j0 * D + j1) * D;
            float a0v = wrow * wu0, a1v = wrow * wu1;
            if (in_pair && (o == 0 || o == 2)) {
                red_add_v2(acc + row + iu, a0v, a1v);
            } else if (in_pair && o == 1) {
                red_add_v4(acc + row + (iu & ~3), 0.0f, a0v, a1v, 0.0f);
            } else {
                if ((unsigned)iu < (unsigned)D)       atomicAdd(acc + row + iu,     a0v);
                if ((unsigned)(iu + 1) < (unsigned)D) atomicAdd(acc + row + iu + 1, a1v);
            }
        }
    }
}

__global__ void zero_kernel(float4* __restrict__ out, int n4) {
    int i = blockIdx.x * blockDim.x + threadIdx.x;
    if (i < n4) out[i] = make_float4(0.f, 0.f, 0.f, 0.f);
}

__global__ void finalize_kernel(const float* __restrict__ img,
                                const float* __restrict__ eff,
                                float* __restrict__ out, int n) {
    int i = blockIdx.x * blockDim.x + threadIdx.x;
    if (i < n) out[i] = img[i] / (eff[i] + 1e-8f) * out[i];
}

extern "C" void kernel_launch(void* const* d_in, const int* in_sizes, int n_in,
                              void* d_out, int out_size) {
    const float* image  = (const float*)d_in[0];
    const float* eff    = (const float*)d_in[1];
    const float* center = (const float*)d_in[3];
    const float* size   = (const float*)d_in[4];
    const float* xlors  = (const float*)d_in[5];
    const float* ylors  = (const float*)d_in[6];
    const float* zlors  = (const float*)d_in[7];
    float* out = (float*)d_out;

    int nx = in_sizes[5] / 6;
    int ny = in_sizes[6] / 6;
    int nz = in_sizes[7] / 6;

    int n4 = out_size / 4;
    zero_kernel<<<(n4 + 255) / 256, 256>>>((float4*)out, n4);

    int total_warps = nx + ny + nz;
    int blocks = (total_warps + NWARP_PER_BLK - 1) / NWARP_PER_BLK;
    lor_all_kernel<<<blocks, NWARP_PER_BLK * 32>>>(
        xlors, ylors, zlors, nx, ny, nz, image, center, size, out);

    finalize_kernel<<<(out_size + 255) / 256, 256>>>(image, eff, out, out_size);
}

// round 6
// speedup vs baseline: 1.1587x; 1.1587x over previous
#include <cuda_runtime.h>
#include <math.h>

#define D 192
#define S_SAMPLES 96
#define NWARP_PER_BLK 8
#define KW_CONST 1.6925687506f  // sqrt(9/pi)

static __device__ __forceinline__ void red_add_v2(float* addr, float a, float b) {
    asm volatile("red.global.add.v2.f32 [%0], {%1, %2};"
                 :: "l"(addr), "f"(a), "f"(b) : "memory");
}
static __device__ __forceinline__ void red_add_v4(float* addr, float a, float b, float c, float d) {
    asm volatile("red.global.add.v4.f32 [%0], {%1, %2, %3, %4};"
                 :: "l"(addr), "f"(a), "f"(b), "f"(c), "f"(d) : "memory");
}

static __device__ __forceinline__ int iclamp(int v) {
    return min(max(v, 0), D - 1);
}

// PERM0 (z-set): axes (x,y | z)   PERM1 (x-set): (y,z | x)   PERM2 (y-set): (y,x | z)
// linear index into original volume = (i0*D + i1)*D + iu
template<int PERM>
__global__ void __launch_bounds__(NWARP_PER_BLK * 32)
lor_kernel(const float* __restrict__ lors,
           const float* __restrict__ img,
           const float* __restrict__ center,
           const float* __restrict__ size,
           float* __restrict__ acc,
           int n)
{
    int warp = (blockIdx.x * blockDim.x + threadIdx.x) >> 5;
    int lane = threadIdx.x & 31;
    if (warp >= n) return;

    const float* L = lors + (size_t)warp * 6;
    float p1x = L[0], p1y = L[1], p1z = L[2];
    float p2x = L[3], p2y = L[4], p2z = L[5];

    float sx = size[0], sy = size[1], sz = size[2];
    float dx = p2x - p1x, dy = p2y - p1y, dz = p2z - p1z;
    float seg = sqrtf(dx * dx + dy * dy + dz * dz) * (1.0f / (float)S_SAMPLES);

    // voxel-space line: w_a(t) = c_a + t*m_a  (divisions hoisted per warp)
    float ivx = (float)D / sx, ivy = (float)D / sy, ivz = (float)D / sz;
    float cxw = (p1x - (center[0] - 0.5f * sx)) * ivx - 0.5f;
    float cyw = (p1y - (center[1] - 0.5f * sy)) * ivy - 0.5f;
    float czw = (p1z - (center[2] - 0.5f * sz)) * ivz - 0.5f;
    float mxw = dx * ivx, myw = dy * ivy, mzw = dz * ivz;

    float c0, c1, cu, m0, m1, mu;
    if (PERM == 0)      { c0 = cxw; c1 = cyw; cu = czw; m0 = mxw; m1 = myw; mu = mzw; }
    else if (PERM == 1) { c0 = cyw; c1 = czw; cu = cxw; m0 = myw; m1 = mzw; mu = mxw; }
    else                { c0 = cyw; c1 = cxw; cu = czw; m0 = myw; m1 = mxw; mu = mzw; }

    // ================= gather pass =================
    float sum = 0.0f;
    #pragma unroll
    for (int k = 0; k < 3; k++) {
        float t = ((float)(lane + 32 * k) + 0.5f) * (1.0f / (float)S_SAMPLES);
        float w0 = fmaf(t, m0, c0);
        float w1 = fmaf(t, m1, c1);
        float wu = fmaf(t, mu, cu);
        float f0 = floorf(w0), f1 = floorf(w1), fu = floorf(wu);
        int i0 = (int)f0, i1 = (int)f1, iu = (int)fu;
        float r0 = w0 - f0, r1 = w1 - f1, ru = wu - fu;

        int  o        = iu & 3;
        bool straddle = (o == 3);
        int  base     = (max(iu, 0)) & ~3;   // iu in [-1, D-1] by geometry
        int  eoff     = min(iu + 1, D - 1);

        float wu0g = (iu >= 0)    ? (1.0f - ru) : 0.0f;
        float wu1g = (iu + 1 < D) ? ru          : 0.0f;
        // place (wu0g, wu1g) at positions (o, o+1) of a 4-vector; WE spills at o==3
        float W0 = (o == 0) ? wu0g : 0.0f;
        float W1 = (o == 0) ? wu1g : ((o == 1) ? wu0g : 0.0f);
        float W2 = (o == 1) ? wu1g : ((o == 2) ? wu0g : 0.0f);
        float W3 = (o == 2) ? wu1g : (straddle ? wu0g : 0.0f);
        float WE = straddle ? wu1g : 0.0f;

        float A0 = ((unsigned)i0       < (unsigned)D) ? (1.0f - r0) : 0.0f;
        float A1 = ((unsigned)(i0 + 1) < (unsigned)D) ? r0          : 0.0f;
        float B0 = ((unsigned)i1       < (unsigned)D) ? (1.0f - r1) : 0.0f;
        float B1 = ((unsigned)(i1 + 1) < (unsigned)D) ? r1          : 0.0f;
        int I0 = iclamp(i0), I1 = iclamp(i0 + 1);
        int J0 = iclamp(i1), J1 = iclamp(i1 + 1);

        int rowIdx[4] = { (I0 * D + J0) * D, (I0 * D + J1) * D,
                          (I1 * D + J0) * D, (I1 * D + J1) * D };
        float rowW[4] = { A0 * B0, A0 * B1, A1 * B0, A1 * B1 };

        #pragma unroll
        for (int c = 0; c < 4; c++) {
            const float4 v = *reinterpret_cast<const float4*>(img + rowIdx[c] + base);
            float acc4 = v.x * W0 + v.y * W1 + v.z * W2 + v.w * W3;
            if (straddle) acc4 += img[rowIdx[c] + eoff] * WE;
            sum += rowW[c] * acc4;
        }
    }

    #pragma unroll
    for (int off = 16; off > 0; off >>= 1)
        sum += __shfl_xor_sync(0xffffffffu, sum, off);

    float a = seg * KW_CONST;
    float contrib = sum * a * a;

    // ================= scatter pass (recompute coords; R2-style width-adaptive atomics,
    // selected by predicates so ptxas emits guarded REDs, no branch ladders) =================
    #pragma unroll
    for (int k = 0; k < 3; k++) {
        float t = ((float)(lane + 32 * k) + 0.5f) * (1.0f / (float)S_SAMPLES);
        float w0 = fmaf(t, m0, c0);
        float w1 = fmaf(t, m1, c1);
        float wu = fmaf(t, mu, cu);
        float f0 = floorf(w0), f1 = floorf(w1), fu = floorf(wu);
        int i0 = (int)f0, i1 = (int)f1, iu = (int)fu;
        float r0 = w0 - f0, r1 = w1 - f1, ru = wu - fu;

        int o = iu & 3;
        bool in_pair  = (iu >= 0) && (iu < D - 1);
        bool use_v2   = in_pair && (o == 0 || o == 2);   // 8B-aligned pair at iu
        bool use_v4   = in_pair && (o == 1);             // padded v4 at base
        bool lo_ok    = (unsigned)iu       < (unsigned)D;
        bool hi_ok    = (unsigned)(iu + 1) < (unsigned)D;
        int  base     = (max(iu, 0)) & ~3;
        int  ilo      = iclamp(iu);
        int  ihi      = iclamp(iu + 1);

        float a0s = (1.0f - ru) * contrib;
        float a1s = ru * contrib;

        float A0 = ((unsigned)i0       < (unsigned)D) ? (1.0f - r0) : 0.0f;
        float A1 = ((unsigned)(i0 + 1) < (unsigned)D) ? r0          : 0.0f;
        float B0 = ((unsigned)i1       < (unsigned)D) ? (1.0f - r1) : 0.0f;
        float B1 = ((unsigned)(i1 + 1) < (unsigned)D) ? r1          : 0.0f;
        int I0 = iclamp(i0), I1 = iclamp(i0 + 1);
        int J0 = iclamp(i1), J1 = iclamp(i1 + 1);

        int rowIdx[4] = { (I0 * D + J0) * D, (I0 * D + J1) * D,
                          (I1 * D + J0) * D, (I1 * D + J1) * D };
        float rowW[4] = { A0 * B0, A0 * B1, A1 * B0, A1 * B1 };

        #pragma unroll
        for (int c = 0; c < 4; c++) {
            float rw = rowW[c];
            bool rw_nz = (rw != 0.0f);
            float v0 = rw * a0s, v1 = rw * a1s;
            if (use_v2 && rw_nz) {
                red_add_v2(acc + rowIdx[c] + iu, v0, v1);
            }
            if (use_v4 && rw_nz) {
                red_add_v4(acc + rowIdx[c] + base, 0.0f, v0, v1, 0.0f);
            }
            if (!use_v2 && !use_v4) {
                if (lo_ok && rw_nz) atomicAdd(acc + rowIdx[c] + ilo, v0);
                if (hi_ok && rw_nz) atomicAdd(acc + rowIdx[c] + ihi, v1);
            }
        }
    }
}

__global__ void zero_kernel(float4* __restrict__ out, int n4) {
    int i = blockIdx.x * blockDim.x + threadIdx.x;
    if (i < n4) out[i] = make_float4(0.f, 0.f, 0.f, 0.f);
}

__global__ void finalize_kernel(const float* __restrict__ img,
                                const float* __restrict__ eff,
                                float* __restrict__ out, int n) {
    int i = blockIdx.x * blockDim.x + threadIdx.x;
    if (i < n) out[i] = img[i] / (eff[i] + 1e-8f) * out[i];
}

extern "C" void kernel_launch(void* const* d_in, const int* in_sizes, int n_in,
                              void* d_out, int out_size) {
    const float* image  = (const float*)d_in[0];
    const float* eff    = (const float*)d_in[1];
    const float* center = (const float*)d_in[3];
    const float* size   = (const float*)d_in[4];
    const float* xlors  = (const float*)d_in[5];
    const float* ylors  = (const float*)d_in[6];
    const float* zlors  = (const float*)d_in[7];
    float* out = (float*)d_out;

    int nx = in_sizes[5] / 6;
    int ny = in_sizes[6] / 6;
    int nz = in_sizes[7] / 6;

    int n4 = out_size / 4;
    zero_kernel<<<(n4 + 255) / 256, 256>>>((float4*)out, n4);

    const int threads = NWARP_PER_BLK * 32;
    lor_kernel<0><<<(nz + NWARP_PER_BLK - 1) / NWARP_PER_BLK, threads>>>(
        zlors, image, center, size, out, nz);
    lor_kernel<1><<<(nx + NWARP_PER_BLK - 1) / NWARP_PER_BLK, threads>>>(
        xlors, image, center, size, out, nx);
    lor_kernel<2><<<(ny + NWARP_PER_BLK - 1) / NWARP_PER_BLK, threads>>>(
        ylors, image, center, size, out, ny);

    finalize_kernel<<<(out_size + 255) / 256, 256>>>(image, eff, out, out_size);
}

// round 7
// speedup vs baseline: 1.2178x; 1.0510x over previous
#include <cuda_runtime.h>
#include <math.h>

#define D 192
#define S_SAMPLES 96
#define NWARP_PER_BLK 8
#define KW_CONST 1.6925687506f  // sqrt(9/pi)

static __device__ __forceinline__ void red_add_v2(float* addr, float a, float b) {
    asm volatile("red.global.add.v2.f32 [%0], {%1, %2};"
                 :: "l"(addr), "f"(a), "f"(b) : "memory");
}
static __device__ __forceinline__ void red_add_v4(float* addr, float a, float b, float c, float d) {
    asm volatile("red.global.add.v4.f32 [%0], {%1, %2, %3, %4};"
                 :: "l"(addr), "f"(a), "f"(b), "f"(c), "f"(d) : "memory");
}

static __device__ __forceinline__ int iclamp(int v) {
    return min(max(v, 0), D - 1);
}

// PERM0 (z-set): axes (x,y | z)   PERM1 (x-set): (y,z | x)   PERM2 (y-set): (y,x | z)
// linear index into original volume = (i0*D + i1)*D + iu
template<int PERM>
__global__ void __launch_bounds__(NWARP_PER_BLK * 32, 5)
lor_kernel(const float* __restrict__ lors,
           const float* __restrict__ img,
           const float* __restrict__ center,
           const float* __restrict__ size,
           float* __restrict__ acc,
           int n)
{
    int warp = (blockIdx.x * blockDim.x + threadIdx.x) >> 5;
    int lane = threadIdx.x & 31;
    if (warp >= n) return;

    const float* L = lors + (size_t)warp * 6;
    float p1x = L[0], p1y = L[1], p1z = L[2];
    float p2x = L[3], p2y = L[4], p2z = L[5];

    float sx = size[0], sy = size[1], sz = size[2];
    float dx = p2x - p1x, dy = p2y - p1y, dz = p2z - p1z;
    float seg = sqrtf(dx * dx + dy * dy + dz * dz) * (1.0f / (float)S_SAMPLES);

    // voxel-space line: w_a(t) = c_a + t*m_a  (divisions hoisted per warp)
    float ivx = (float)D / sx, ivy = (float)D / sy, ivz = (float)D / sz;
    float cxw = (p1x - (center[0] - 0.5f * sx)) * ivx - 0.5f;
    float cyw = (p1y - (center[1] - 0.5f * sy)) * ivy - 0.5f;
    float czw = (p1z - (center[2] - 0.5f * sz)) * ivz - 0.5f;
    float mxw = dx * ivx, myw = dy * ivy, mzw = dz * ivz;

    float c0, c1, cu, m0, m1, mu;
    if (PERM == 0)      { c0 = cxw; c1 = cyw; cu = czw; m0 = mxw; m1 = myw; mu = mzw; }
    else if (PERM == 1) { c0 = cyw; c1 = czw; cu = cxw; m0 = myw; m1 = mzw; mu = mxw; }
    else                { c0 = cyw; c1 = cxw; cu = czw; m0 = myw; m1 = mxw; mu = mzw; }

    // ================= gather pass (fully unrolled: MLP feeds the dependent sum) ======
    float sum = 0.0f;
    #pragma unroll
    for (int k = 0; k < 3; k++) {
        float t = ((float)(lane + 32 * k) + 0.5f) * (1.0f / (float)S_SAMPLES);
        float w0 = fmaf(t, m0, c0);
        float w1 = fmaf(t, m1, c1);
        float wu = fmaf(t, mu, cu);
        float f0 = floorf(w0), f1 = floorf(w1), fu = floorf(wu);
        int i0 = (int)f0, i1 = (int)f1, iu = (int)fu;
        float r0 = w0 - f0, r1 = w1 - f1, ru = wu - fu;

        int  o        = iu & 3;
        bool straddle = (o == 3);
        int  base     = (max(iu, 0)) & ~3;   // iu in [-1, D-1] by geometry
        int  eoff     = min(iu + 1, D - 1);

        float wu0g = (iu >= 0)    ? (1.0f - ru) : 0.0f;
        float wu1g = (iu + 1 < D) ? ru          : 0.0f;
        // place (wu0g, wu1g) at positions (o, o+1) of a 4-vector; WE spills at o==3
        float W0 = (o == 0) ? wu0g : 0.0f;
        float W1 = (o == 0) ? wu1g : ((o == 1) ? wu0g : 0.0f);
        float W2 = (o == 1) ? wu1g : ((o == 2) ? wu0g : 0.0f);
        float W3 = (o == 2) ? wu1g : (straddle ? wu0g : 0.0f);
        float WE = straddle ? wu1g : 0.0f;

        float A0 = ((unsigned)i0       < (unsigned)D) ? (1.0f - r0) : 0.0f;
        float A1 = ((unsigned)(i0 + 1) < (unsigned)D) ? r0          : 0.0f;
        float B0 = ((unsigned)i1       < (unsigned)D) ? (1.0f - r1) : 0.0f;
        float B1 = ((unsigned)(i1 + 1) < (unsigned)D) ? r1          : 0.0f;
        int I0 = iclamp(i0), I1 = iclamp(i0 + 1);
        int J0 = iclamp(i1), J1 = iclamp(i1 + 1);

        int rowIdx[4] = { (I0 * D + J0) * D, (I0 * D + J1) * D,
                          (I1 * D + J0) * D, (I1 * D + J1) * D };
        float rowW[4] = { A0 * B0, A0 * B1, A1 * B0, A1 * B1 };

        #pragma unroll
        for (int c = 0; c < 4; c++) {
            const float4 v = *reinterpret_cast<const float4*>(img + rowIdx[c] + base);
            float acc4 = v.x * W0 + v.y * W1 + v.z * W2 + v.w * W3;
            if (straddle) acc4 += img[rowIdx[c] + eoff] * WE;
            sum += rowW[c] * acc4;
        }
    }

    #pragma unroll
    for (int off = 16; off > 0; off >>= 1)
        sum += __shfl_xor_sync(0xffffffffu, sum, off);

    float a = seg * KW_CONST;
    float contrib = sum * a * a;

    // ================= scatter pass: NOT unrolled (REDs have no results to overlap;
    // unrolling only triples live state) ==========================================
    #pragma unroll 1
    for (int k = 0; k < 3; k++) {
        float t = ((float)(lane + 32 * k) + 0.5f) * (1.0f / (float)S_SAMPLES);
        float w0 = fmaf(t, m0, c0);
        float w1 = fmaf(t, m1, c1);
        float wu = fmaf(t, mu, cu);
        float f0 = floorf(w0), f1 = floorf(w1), fu = floorf(wu);
        int i0 = (int)f0, i1 = (int)f1, iu = (int)fu;
        float r0 = w0 - f0, r1 = w1 - f1, ru = wu - fu;

        int o = iu & 3;
        bool in_pair  = (iu >= 0) && (iu < D - 1);
        bool use_v2   = in_pair && (o == 0 || o == 2);   // 8B-aligned pair at iu
        bool use_v4   = in_pair && (o == 1);             // padded v4 at base
        bool lo_ok    = (unsigned)iu       < (unsigned)D;
        bool hi_ok    = (unsigned)(iu + 1) < (unsigned)D;
        int  base     = (max(iu, 0)) & ~3;
        int  ilo      = iclamp(iu);
        int  ihi      = iclamp(iu + 1);

        float a0s = (1.0f - ru) * contrib;
        float a1s = ru * contrib;

        float A0 = ((unsigned)i0       < (unsigned)D) ? (1.0f - r0) : 0.0f;
        float A1 = ((unsigned)(i0 + 1) < (unsigned)D) ? r0          : 0.0f;
        float B0 = ((unsigned)i1       < (unsigned)D) ? (1.0f - r1) : 0.0f;
        float B1 = ((unsigned)(i1 + 1) < (unsigned)D) ? r1          : 0.0f;
        int I0 = iclamp(i0), I1 = iclamp(i0 + 1);
        int J0 = iclamp(i1), J1 = iclamp(i1 + 1);

        int rowIdx[4] = { (I0 * D + J0) * D, (I0 * D + J1) * D,
                          (I1 * D + J0) * D, (I1 * D + J1) * D };
        float rowW[4] = { A0 * B0, A0 * B1, A1 * B0, A1 * B1 };

        #pragma unroll
        for (int c = 0; c < 4; c++) {
            float rw = rowW[c];
            float v0 = rw * a0s, v1 = rw * a1s;
            if (use_v2) {
                red_add_v2(acc + rowIdx[c] + iu, v0, v1);
            }
            if (use_v4) {
                red_add_v4(acc + rowIdx[c] + base, 0.0f, v0, v1, 0.0f);
            }
            if (!use_v2 && !use_v4) {
                bool rw_nz = (rw != 0.0f);
                if (lo_ok && rw_nz) atomicAdd(acc + rowIdx[c] + ilo, v0);
                if (hi_ok && rw_nz) atomicAdd(acc + rowIdx[c] + ihi, v1);
            }
        }
    }
}

__global__ void zero_kernel(float4* __restrict__ out, int n4) {
    int i = blockIdx.x * blockDim.x + threadIdx.x;
    if (i < n4) out[i] = make_float4(0.f, 0.f, 0.f, 0.f);
}

__global__ void finalize_kernel(const float* __restrict__ img,
                                const float* __restrict__ eff,
                                float* __restrict__ out, int n) {
    int i = blockIdx.x * blockDim.x + threadIdx.x;
    if (i < n) out[i] = img[i] / (eff[i] + 1e-8f) * out[i];
}

extern "C" void kernel_launch(void* const* d_in, const int* in_sizes, int n_in,
                              void* d_out, int out_size) {
    const float* image  = (const float*)d_in[0];
    const float* eff    = (const float*)d_in[1];
    const float* center = (const float*)d_in[3];
    const float* size   = (const float*)d_in[4];
    const float* xlors  = (const float*)d_in[5];
    const float* ylors  = (const float*)d_in[6];
    const float* zlors  = (const float*)d_in[7];
    float* out = (float*)d_out;

    int nx = in_sizes[5] / 6;
    int ny = in_sizes[6] / 6;
    int nz = in_sizes[7] / 6;

    int n4 = out_size / 4;
    zero_kernel<<<(n4 + 255) / 256, 256>>>((float4*)out, n4);

    const int threads = NWARP_PER_BLK * 32;
    lor_kernel<0><<<(nz + NWARP_PER_BLK - 1) / NWARP_PER_BLK, threads>>>(
        zlors, image, center, size, out, nz);
    lor_kernel<1><<<(nx + NWARP_PER_BLK - 1) / NWARP_PER_BLK, threads>>>(
        xlors, image, center, size, out, nx);
    lor_kernel<2><<<(ny + NWARP_PER_BLK - 1) / NWARP_PER_BLK, threads>>>(
        ylors, image, center, size, out, ny);

    finalize_kernel<<<(out_size + 255) / 256, 256>>>(image, eff, out, out_size);
}

// round 8
// speedup vs baseline: 1.2510x; 1.0273x over previous
#include <cuda_runtime.h>
#include <math.h>

#define D 192
#define D3 (D * D * D)
#define S_SAMPLES 96
#define NWARP_PER_BLK 8
#define KW_CONST 1.6925687506f  // sqrt(9/pi)

// Redundant pair image: pairs[n] = (img[n], img[n+1])  (56.6 MB, .bss)
__device__ float2 g_pairs[D3];

static __device__ __forceinline__ void red_add_v2(float* addr, float a, float b) {
    asm volatile("red.global.add.v2.f32 [%0], {%1, %2};"
                 :: "l"(addr), "f"(a), "f"(b) : "memory");
}
static __device__ __forceinline__ void red_add_v4(float* addr, float a, float b, float c, float d) {
    asm volatile("red.global.add.v4.f32 [%0], {%1, %2, %3, %4};"
                 :: "l"(addr), "f"(a), "f"(b), "f"(c), "f"(d) : "memory");
}

static __device__ __forceinline__ int iclamp(int v) {
    return min(max(v, 0), D - 1);
}

// Build pair image + zero accumulator in one pass (grid-stride).
__global__ void prep_kernel(const float4* __restrict__ img4,
                            const float* __restrict__ img,
                            float4* __restrict__ acc4) {
    int n4 = D3 / 4;
    for (int i = blockIdx.x * blockDim.x + threadIdx.x; i < n4;
         i += gridDim.x * blockDim.x) {
        float4 a = img4[i];
        float b = img[min(4 * i + 4, D3 - 1)];
        float2* p = g_pairs + 4 * i;
        *reinterpret_cast<float4*>(p)     = make_float4(a.x, a.y, a.y, a.z);
        *reinterpret_cast<float4*>(p + 2) = make_float4(a.z, a.w, a.w, b);
        acc4[i] = make_float4(0.f, 0.f, 0.f, 0.f);
    }
}

// PERM0 (z-set): axes (x,y | z)   PERM1 (x-set): (y,z | x)   PERM2 (y-set): (y,x | z)
// linear index into original volume = (i0*D + i1)*D + iu
template<int PERM>
__global__ void __launch_bounds__(NWARP_PER_BLK * 32, 6)
lor_kernel(const float* __restrict__ lors,
           const float* __restrict__ center,
           const float* __restrict__ size,
           float* __restrict__ acc,
           int n)
{
    int warp = (blockIdx.x * blockDim.x + threadIdx.x) >> 5;
    int lane = threadIdx.x & 31;
    if (warp >= n) return;

    const float* L = lors + (size_t)warp * 6;
    float p1x = L[0], p1y = L[1], p1z = L[2];
    float p2x = L[3], p2y = L[4], p2z = L[5];

    float sx = size[0], sy = size[1], sz = size[2];
    float dx = p2x - p1x, dy = p2y - p1y, dz = p2z - p1z;
    float seg = sqrtf(dx * dx + dy * dy + dz * dz) * (1.0f / (float)S_SAMPLES);

    // voxel-space line: w_a(t) = c_a + t*m_a  (divisions hoisted per warp)
    float ivx = (float)D / sx, ivy = (float)D / sy, ivz = (float)D / sz;
    float cxw = (p1x - (center[0] - 0.5f * sx)) * ivx - 0.5f;
    float cyw = (p1y - (center[1] - 0.5f * sy)) * ivy - 0.5f;
    float czw = (p1z - (center[2] - 0.5f * sz)) * ivz - 0.5f;
    float mxw = dx * ivx, myw = dy * ivy, mzw = dz * ivz;

    float c0, c1, cu, m0, m1, mu;
    if (PERM == 0)      { c0 = cxw; c1 = cyw; cu = czw; m0 = mxw; m1 = myw; mu = mzw; }
    else if (PERM == 1) { c0 = cyw; c1 = czw; cu = cxw; m0 = myw; m1 = mzw; mu = mxw; }
    else                { c0 = cyw; c1 = cxw; cu = czw; m0 = myw; m1 = mxw; mu = mzw; }

    // ================= gather pass: 1 aligned float2 load per row =================
    float sum = 0.0f;
    #pragma unroll
    for (int k = 0; k < 3; k++) {
        float t = ((float)(lane + 32 * k) + 0.5f) * (1.0f / (float)S_SAMPLES);
        float w0 = fmaf(t, m0, c0);
        float w1 = fmaf(t, m1, c1);
        float wu = fmaf(t, mu, cu);
        float f0 = floorf(w0), f1 = floorf(w1), fu = floorf(wu);
        int i0 = (int)f0, i1 = (int)f1, iu = (int)fu;
        float r0 = w0 - f0, r1 = w1 - f1, ru = wu - fu;

        // iu in [-1, D-1] by geometry.
        //   iu >= 0:  val = p.x*(1-ru) + p.y*ru   (p at iu; p.y masked at iu==D-1)
        //   iu == -1: val = p.x*ru                (p at 0; p.x == img[row][0])
        int   ilo = max(iu, 0);
        float wlo = (iu >= 0) ? (1.0f - ru) : ru;
        float whi = (iu >= 0 && iu + 1 < D) ? ru : 0.0f;

        float A0 = ((unsigned)i0       < (unsigned)D) ? (1.0f - r0) : 0.0f;
        float A1 = ((unsigned)(i0 + 1) < (unsigned)D) ? r0          : 0.0f;
        float B0 = ((unsigned)i1       < (unsigned)D) ? (1.0f - r1) : 0.0f;
        float B1 = ((unsigned)(i1 + 1) < (unsigned)D) ? r1          : 0.0f;
        int I0 = iclamp(i0), I1 = iclamp(i0 + 1);
        int J0 = iclamp(i1), J1 = iclamp(i1 + 1);

        int rowIdx[4] = { (I0 * D + J0) * D, (I0 * D + J1) * D,
                          (I1 * D + J0) * D, (I1 * D + J1) * D };
        float rowW[4] = { A0 * B0, A0 * B1, A1 * B0, A1 * B1 };

        #pragma unroll
        for (int c = 0; c < 4; c++) {
            float2 p = g_pairs[rowIdx[c] + ilo];
            sum += rowW[c] * (p.x * wlo + p.y * whi);
        }
    }

    #pragma unroll
    for (int off = 16; off > 0; off >>= 1)
        sum += __shfl_xor_sync(0xffffffffu, sum, off);

    float a = seg * KW_CONST;
    float contrib = sum * a * a;

    // ================= scatter pass (width-adaptive predicated REDs) =================
    #pragma unroll 1
    for (int k = 0; k < 3; k++) {
        float t = ((float)(lane + 32 * k) + 0.5f) * (1.0f / (float)S_SAMPLES);
        float w0 = fmaf(t, m0, c0);
        float w1 = fmaf(t, m1, c1);
        float wu = fmaf(t, mu, cu);
        float f0 = floorf(w0), f1 = floorf(w1), fu = floorf(wu);
        int i0 = (int)f0, i1 = (int)f1, iu = (int)fu;
        float r0 = w0 - f0, r1 = w1 - f1, ru = wu - fu;

        int o = iu & 3;
        bool in_pair  = (iu >= 0) && (iu < D - 1);
        bool use_v2   = in_pair && (o == 0 || o == 2);   // 8B-aligned pair at iu
        bool use_v4   = in_pair && (o == 1);             // padded v4 at base
        bool lo_ok    = (unsigned)iu       < (unsigned)D;
        bool hi_ok    = (unsigned)(iu + 1) < (unsigned)D;
        int  base     = (max(iu, 0)) & ~3;
        int  ilo      = iclamp(iu);
        int  ihi      = iclamp(iu + 1);

        float a0s = (1.0f - ru) * contrib;
        float a1s = ru * contrib;

        float A0 = ((unsigned)i0       < (unsigned)D) ? (1.0f - r0) : 0.0f;
        float A1 = ((unsigned)(i0 + 1) < (unsigned)D) ? r0          : 0.0f;
        float B0 = ((unsigned)i1       < (unsigned)D) ? (1.0f - r1) : 0.0f;
        float B1 = ((unsigned)(i1 + 1) < (unsigned)D) ? r1          : 0.0f;
        int I0 = iclamp(i0), I1 = iclamp(i0 + 1);
        int J0 = iclamp(i1), J1 = iclamp(i1 + 1);

        int rowIdx[4] = { (I0 * D + J0) * D, (I0 * D + J1) * D,
                          (I1 * D + J0) * D, (I1 * D + J1) * D };
        float rowW[4] = { A0 * B0, A0 * B1, A1 * B0, A1 * B1 };

        #pragma unroll
        for (int c = 0; c < 4; c++) {
            float rw = rowW[c];
            float v0 = rw * a0s, v1 = rw * a1s;
            if (use_v2) {
                red_add_v2(acc + rowIdx[c] + iu, v0, v1);
            }
            if (use_v4) {
                red_add_v4(acc + rowIdx[c] + base, 0.0f, v0, v1, 0.0f);
            }
            if (!use_v2 && !use_v4) {
                bool rw_nz = (rw != 0.0f);
                if (lo_ok && rw_nz) atomicAdd(acc + rowIdx[c] + ilo, v0);
                if (hi_ok && rw_nz) atomicAdd(acc + rowIdx[c] + ihi, v1);
            }
        }
    }
}

__global__ void finalize_kernel(const float* __restrict__ img,
                                const float* __restrict__ eff,
                                float* __restrict__ out, int n) {
    int i = blockIdx.x * blockDim.x + threadIdx.x;
    if (i < n) out[i] = img[i] / (eff[i] + 1e-8f) * out[i];
}

extern "C" void kernel_launch(void* const* d_in, const int* in_sizes, int n_in,
                              void* d_out, int out_size) {
    const float* image  = (const float*)d_in[0];
    const float* eff    = (const float*)d_in[1];
    const float* center = (const float*)d_in[3];
    const float* size   = (const float*)d_in[4];
    const float* xlors  = (const float*)d_in[5];
    const float* ylors  = (const float*)d_in[6];
    const float* zlors  = (const float*)d_in[7];
    float* out = (float*)d_out;

    int nx = in_sizes[5] / 6;
    int ny = in_sizes[6] / 6;
    int nz = in_sizes[7] / 6;

    // build pair image + zero accumulator
    prep_kernel<<<2048, 256>>>((const float4*)image, image, (float4*)out);

    const int threads = NWARP_PER_BLK * 32;
    lor_kernel<0><<<(nz + NWARP_PER_BLK - 1) / NWARP_PER_BLK, threads>>>(
        zlors, center, size, out, nz);
    lor_kernel<1><<<(nx + NWARP_PER_BLK - 1) / NWARP_PER_BLK, threads>>>(
        xlors, center, size, out, nx);
    lor_kernel<2><<<(ny + NWARP_PER_BLK - 1) / NWARP_PER_BLK, threads>>>(
        ylors, center, size, out, ny);

    finalize_kernel<<<(out_size + 255) / 256, 256>>>(image, eff, out, out_size);
}

// round 9
// speedup vs baseline: 1.3307x; 1.0637x over previous
#include <cuda_runtime.h>
#include <math.h>

#define D 192
#define D3 (D * D * D)
#define S_SAMPLES 96
#define NWARP_PER_BLK 8
#define KW_CONST 1.6925687506f  // sqrt(9/pi)

// Redundant pair image: pairs[n] = (img[n], img[n+1])  (56.6 MB)
__device__ float2 g_pairs[D3];
// Shifted accumulator: g_accO[m] accumulates contributions to voxel m+1 (28.3 MB)
__device__ float g_accO[D3];

static __device__ __forceinline__ void red_add_v2(float* addr, float a, float b) {
    asm volatile("red.global.add.v2.f32 [%0], {%1, %2};"
                 :: "l"(addr), "f"(a), "f"(b) : "memory");
}

static __device__ __forceinline__ int iclamp(int v) {
    return min(max(v, 0), D - 1);
}

// Build pair image + zero both accumulators (grid-stride).
__global__ void prep_kernel(const float4* __restrict__ img4,
                            const float* __restrict__ img,
                            float4* __restrict__ accE4) {
    int n4 = D3 / 4;
    float4 z = make_float4(0.f, 0.f, 0.f, 0.f);
    for (int i = blockIdx.x * blockDim.x + threadIdx.x; i < n4;
         i += gridDim.x * blockDim.x) {
        float4 a = img4[i];
        float b = img[min(4 * i + 4, D3 - 1)];
        float2* p = g_pairs + 4 * i;
        *reinterpret_cast<float4*>(p)     = make_float4(a.x, a.y, a.y, a.z);
        *reinterpret_cast<float4*>(p + 2) = make_float4(a.z, a.w, a.w, b);
        accE4[i] = z;
        reinterpret_cast<float4*>(g_accO)[i] = z;
    }
}

// PERM0 (z-set): axes (x,y | z)   PERM1 (x-set): (y,z | x)   PERM2 (y-set): (y,x | z)
// linear index into original volume = (i0*D + i1)*D + iu
template<int PERM>
__global__ void __launch_bounds__(NWARP_PER_BLK * 32, 6)
lor_kernel(const float* __restrict__ lors,
           const float* __restrict__ center,
           const float* __restrict__ size,
           float* __restrict__ accE,
           int n)
{
    int warp = (blockIdx.x * blockDim.x + threadIdx.x) >> 5;
    int lane = threadIdx.x & 31;
    if (warp >= n) return;

    const float* L = lors + (size_t)warp * 6;
    float p1x = L[0], p1y = L[1], p1z = L[2];
    float p2x = L[3], p2y = L[4], p2z = L[5];

    float sx = size[0], sy = size[1], sz = size[2];
    float dx = p2x - p1x, dy = p2y - p1y, dz = p2z - p1z;
    float seg = sqrtf(dx * dx + dy * dy + dz * dz) * (1.0f / (float)S_SAMPLES);

    // voxel-space line: w_a(t) = c_a + t*m_a  (divisions hoisted per warp)
    float ivx = (float)D / sx, ivy = (float)D / sy, ivz = (float)D / sz;
    float cxw = (p1x - (center[0] - 0.5f * sx)) * ivx - 0.5f;
    float cyw = (p1y - (center[1] - 0.5f * sy)) * ivy - 0.5f;
    float czw = (p1z - (center[2] - 0.5f * sz)) * ivz - 0.5f;
    float mxw = dx * ivx, myw = dy * ivy, mzw = dz * ivz;

    float c0, c1, cu, m0, m1, mu;
    if (PERM == 0)      { c0 = cxw; c1 = cyw; cu = czw; m0 = mxw; m1 = myw; mu = mzw; }
    else if (PERM == 1) { c0 = cyw; c1 = czw; cu = cxw; m0 = myw; m1 = mzw; mu = mxw; }
    else                { c0 = cyw; c1 = cxw; cu = czw; m0 = myw; m1 = mxw; mu = mzw; }

    // ================= gather pass: 1 aligned float2 load per row =================
    float sum = 0.0f;
    #pragma unroll
    for (int k = 0; k < 3; k++) {
        float t = ((float)(lane + 32 * k) + 0.5f) * (1.0f / (float)S_SAMPLES);
        float w0 = fmaf(t, m0, c0);
        float w1 = fmaf(t, m1, c1);
        float wu = fmaf(t, mu, cu);
        float f0 = floorf(w0), f1 = floorf(w1), fu = floorf(wu);
        int i0 = (int)f0, i1 = (int)f1, iu = (int)fu;
        float r0 = w0 - f0, r1 = w1 - f1, ru = wu - fu;

        // iu in [-1, D-1] by geometry.
        int   ilo = max(iu, 0);
        float wlo = (iu >= 0) ? (1.0f - ru) : ru;
        float whi = (iu >= 0 && iu + 1 < D) ? ru : 0.0f;

        float A0 = ((unsigned)i0       < (unsigned)D) ? (1.0f - r0) : 0.0f;
        float A1 = ((unsigned)(i0 + 1) < (unsigned)D) ? r0          : 0.0f;
        float B0 = ((unsigned)i1       < (unsigned)D) ? (1.0f - r1) : 0.0f;
        float B1 = ((unsigned)(i1 + 1) < (unsigned)D) ? r1          : 0.0f;
        int I0 = iclamp(i0), I1 = iclamp(i0 + 1);
        int J0 = iclamp(i1), J1 = iclamp(i1 + 1);

        int rowIdx[4] = { (I0 * D + J0) * D, (I0 * D + J1) * D,
                          (I1 * D + J0) * D, (I1 * D + J1) * D };
        float rowW[4] = { A0 * B0, A0 * B1, A1 * B0, A1 * B1 };

        #pragma unroll
        for (int c = 0; c < 4; c++) {
            float2 p = g_pairs[rowIdx[c] + ilo];
            sum += rowW[c] * (p.x * wlo + p.y * whi);
        }
    }

    #pragma unroll
    for (int off = 16; off > 0; off >>= 1)
        sum += __shfl_xor_sync(0xffffffffu, sum, off);

    float a = seg * KW_CONST;
    float contrib = sum * a * a;

    // ========== scatter pass: exactly one aligned red.v2 per row ==========
    // pair base b = max(iu,0): b even -> accE + b (slot m = voxel m)
    //                          b odd  -> g_accO + b - 1 (slot m = voxel m+1)
    // crossing/out-of-range second slots always receive +0.0.
    #pragma unroll 1
    for (int k = 0; k < 3; k++) {
        float t = ((float)(lane + 32 * k) + 0.5f) * (1.0f / (float)S_SAMPLES);
        float w0 = fmaf(t, m0, c0);
        float w1 = fmaf(t, m1, c1);
        float wu = fmaf(t, mu, cu);
        float f0 = floorf(w0), f1 = floorf(w1), fu = floorf(wu);
        int i0 = (int)f0, i1 = (int)f1, iu = (int)fu;
        float r0 = w0 - f0, r1 = w1 - f1, ru = wu - fu;

        int   b   = max(iu, 0);
        float wlo = ((iu >= 0) ? (1.0f - ru) : ru) * contrib;
        float whi = ((iu >= 0 && iu + 1 < D) ? ru : 0.0f) * contrib;

        float* basep = ((b & 1) == 0) ? (accE + b) : (g_accO + (b - 1));

        float A0 = ((unsigned)i0       < (unsigned)D) ? (1.0f - r0) : 0.0f;
        float A1 = ((unsigned)(i0 + 1) < (unsigned)D) ? r0          : 0.0f;
        float B0 = ((unsigned)i1       < (unsigned)D) ? (1.0f - r1) : 0.0f;
        float B1 = ((unsigned)(i1 + 1) < (unsigned)D) ? r1          : 0.0f;
        int I0 = iclamp(i0), I1 = iclamp(i0 + 1);
        int J0 = iclamp(i1), J1 = iclamp(i1 + 1);

        int rowIdx[4] = { (I0 * D + J0) * D, (I0 * D + J1) * D,
                          (I1 * D + J0) * D, (I1 * D + J1) * D };
        float rowW[4] = { A0 * B0, A0 * B1, A1 * B0, A1 * B1 };

        #pragma unroll
        for (int c = 0; c < 4; c++) {
            float rw = rowW[c];
            red_add_v2(basep + rowIdx[c], rw * wlo, rw * whi);
        }
    }
}

__global__ void finalize_kernel(const float* __restrict__ img,
                                const float* __restrict__ eff,
                                float* __restrict__ out, int n) {
    int i = blockIdx.x * blockDim.x + threadIdx.x;
    if (i < n) {
        float bp = out[i] + ((i > 0) ? g_accO[i - 1] : 0.0f);
        out[i] = img[i] / (eff[i] + 1e-8f) * bp;
    }
}

extern "C" void kernel_launch(void* const* d_in, const int* in_sizes, int n_in,
                              void* d_out, int out_size) {
    const float* image  = (const float*)d_in[0];
    const float* eff    = (const float*)d_in[1];
    const float* center = (const float*)d_in[3];
    const float* size   = (const float*)d_in[4];
    const float* xlors  = (const float*)d_in[5];
    const float* ylors  = (const float*)d_in[6];
    const float* zlors  = (const float*)d_in[7];
    float* out = (float*)d_out;

    int nx = in_sizes[5] / 6;
    int ny = in_sizes[6] / 6;
    int nz = in_sizes[7] / 6;

    prep_kernel<<<2048, 256>>>((const float4*)image, image, (float4*)out);

    const int threads = NWARP_PER_BLK * 32;
    lor_kernel<0><<<(nz + NWARP_PER_BLK - 1) / NWARP_PER_BLK, threads>>>(
        zlors, center, size, out, nz);
    lor_kernel<1><<<(nx + NWARP_PER_BLK - 1) / NWARP_PER_BLK, threads>>>(
        xlors, center, size, out, nx);
    lor_kernel<2><<<(ny + NWARP_PER_BLK - 1) / NWARP_PER_BLK, threads>>>(
        ylors, center, size, out, ny);

    finalize_kernel<<<(out_size + 255) / 256, 256>>>(image, eff, out, out_size);
}